// round 9
// baseline (speedup 1.0000x reference)
#include <cuda_runtime.h>
#include <cstdint>

// IFOPooling: h_t = f_t * h_{t-1} + i_t * z_t over S (contiguous), per (b,h) row.
// R8 direction extended: 4 rows fused per 1024-thread CTA (grid 4096). Each
// 256-thread quarter processes one row with its own NAMED barrier + private
// smem slice -> quarters fully decoupled (no cross-row coupling). 32 KB
// contiguous per stream per CTA improves DRAM row-buffer locality. Streaming
// cache hints on all zero-reuse streams.

constexpr int S_LEN  = 2048;
constexpr int QTR    = 256;            // threads per row
constexpr int NROWS  = 4;              // rows per CTA
constexpr int NTHR   = QTR * NROWS;    // 1024
constexpr int PER    = S_LEN / QTR;    // 8 elements per thread
constexpr int NWARP  = QTR / 32;       // 8 warps per row

__global__ __launch_bounds__(NTHR, 2)
void ifo_scan_kernel(const float* __restrict__ f,
                     const float* __restrict__ z,
                     const float* __restrict__ i_,
                     float* __restrict__ out)
{
    const int t    = threadIdx.x;
    const int sub  = t >> 8;                   // which row-quarter (0..3)
    const int st   = t & (QTR - 1);            // thread id within the quarter
    const int lane = t & 31;
    const int warp = (t >> 5) & (NWARP - 1);   // warp id within the quarter

    const size_t row  = (size_t)blockIdx.x * NROWS + sub;
    const size_t base = row * S_LEN + (size_t)st * PER;

    // ---- 6 independent streaming loads, issued before any math ----
    float4 fa = __ldcs(reinterpret_cast<const float4*>(f  + base));
    float4 fb = __ldcs(reinterpret_cast<const float4*>(f  + base + 4));
    float4 za = __ldcs(reinterpret_cast<const float4*>(z  + base));
    float4 zb = __ldcs(reinterpret_cast<const float4*>(z  + base + 4));
    float4 ia = __ldcs(reinterpret_cast<const float4*>(i_ + base));
    float4 ib = __ldcs(reinterpret_cast<const float4*>(i_ + base + 4));

    float fv[PER] = {fa.x, fa.y, fa.z, fa.w, fb.x, fb.y, fb.z, fb.w};
    float xv[PER] = {ia.x * za.x, ia.y * za.y, ia.z * za.z, ia.w * za.w,
                     ib.x * zb.x, ib.y * zb.y, ib.z * zb.z, ib.w * zb.w};

    // ---- Local chunk -> affine pair (A, B): h_out = A*h_in + B ----
    float A = 1.0f, Bc = 0.0f;
    #pragma unroll
    for (int j = 0; j < PER; j++) {
        Bc = fmaf(fv[j], Bc, xv[j]);
        A  = A * fv[j];
    }

    // ---- Intra-warp inclusive scan over pairs ----
    // combine(prev=(Ap,Bp), cur=(Ac,Bc)) = (Ap*Ac, Ac*Bp + Bc)
    float Ai = A, Bi = Bc;
    #pragma unroll
    for (int d = 1; d < 32; d <<= 1) {
        float Au = __shfl_up_sync(0xffffffffu, Ai, d);
        float Bu = __shfl_up_sync(0xffffffffu, Bi, d);
        if (lane >= d) {
            Bi = fmaf(Ai, Bu, Bi);
            Ai = Ai * Au;
        }
    }

    // ---- Cross-warp prefix: per-quarter smem + per-quarter NAMED barrier ----
    __shared__ float sA[NROWS][NWARP];
    __shared__ float sB[NROWS][NWARP];
    if (lane == 31) { sA[sub][warp] = Ai; sB[sub][warp] = Bi; }
    // Named barrier: only this quarter's 256 threads participate (ids 1..4).
    asm volatile("bar.sync %0, %1;" :: "r"(sub + 1), "r"(QTR) : "memory");

    // Exclusive prefix over warps; only the B component matters (h0 = 0).
    float Bw = 0.0f;
    #pragma unroll
    for (int w = 0; w < NWARP; w++) {
        if (w < warp) {
            Bw = fmaf(sA[sub][w], Bw, sB[sub][w]);
        }
    }

    // ---- Thread's exclusive prefix within warp ----
    float Ae = __shfl_up_sync(0xffffffffu, Ai, 1);
    float Be = __shfl_up_sync(0xffffffffu, Bi, 1);
    if (lane == 0) { Ae = 1.0f; Be = 0.0f; }

    // Incoming h for this chunk (h0 = 0): h_in = Ae*Bw + Be
    float h = fmaf(Ae, Bw, Be);

    // ---- Replay chunk from registers, streaming stores ----
    float ov[PER];
    #pragma unroll
    for (int j = 0; j < PER; j++) {
        h = fmaf(fv[j], h, xv[j]);
        ov[j] = h;
    }

    __stcs(reinterpret_cast<float4*>(out + base),
           make_float4(ov[0], ov[1], ov[2], ov[3]));
    __stcs(reinterpret_cast<float4*>(out + base + 4),
           make_float4(ov[4], ov[5], ov[6], ov[7]));
}

extern "C" void kernel_launch(void* const* d_in, const int* in_sizes, int n_in,
                              void* d_out, int out_size)
{
    const float* f = (const float*)d_in[0];
    const float* z = (const float*)d_in[1];
    const float* i = (const float*)d_in[2];
    float* out = (float*)d_out;

    const int n_rows = in_sizes[0] / S_LEN;   // B*H = 16384 (divisible by 4)
    ifo_scan_kernel<<<n_rows / NROWS, NTHR>>>(f, z, i, out);
}

// round 10
// speedup vs baseline: 1.0312x; 1.0312x over previous
#include <cuda_runtime.h>
#include <cstdint>

// IFOPooling: h_t = f_t * h_{t-1} + i_t * z_t over S (contiguous), per (b,h) row.
// R8 optimum (2 rows per 512-thread CTA, per-half named barriers) upgraded to
// Blackwell 256-bit global accesses (ld/st.global.v8.f32): half the LSU
// requests and L1tex wavefronts per byte. Streaming (.cs) policy throughout.

constexpr int S_LEN  = 2048;
constexpr int HALF   = 256;            // threads per row
constexpr int NTHR   = 512;            // 2 rows per CTA
constexpr int PER    = S_LEN / HALF;   // 8 elements per thread
constexpr int NWARP  = HALF / 32;      // 8 warps per row

__device__ __forceinline__ void ldg256_cs(float v[8], const float* p) {
    asm volatile("ld.global.cs.v8.f32 {%0,%1,%2,%3,%4,%5,%6,%7}, [%8];"
                 : "=f"(v[0]), "=f"(v[1]), "=f"(v[2]), "=f"(v[3]),
                   "=f"(v[4]), "=f"(v[5]), "=f"(v[6]), "=f"(v[7])
                 : "l"(p));
}

__device__ __forceinline__ void stg256_cs(float* p, const float v[8]) {
    asm volatile("st.global.cs.v8.f32 [%0], {%1,%2,%3,%4,%5,%6,%7,%8};"
                 :: "l"(p),
                    "f"(v[0]), "f"(v[1]), "f"(v[2]), "f"(v[3]),
                    "f"(v[4]), "f"(v[5]), "f"(v[6]), "f"(v[7])
                 : "memory");
}

__global__ __launch_bounds__(NTHR, 4)
void ifo_scan_kernel(const float* __restrict__ f,
                     const float* __restrict__ z,
                     const float* __restrict__ i_,
                     float* __restrict__ out)
{
    const int t    = threadIdx.x;
    const int sub  = t >> 8;                   // which row-half (0 or 1)
    const int st   = t & (HALF - 1);           // thread id within the half
    const int lane = t & 31;
    const int warp = (t >> 5) & (NWARP - 1);   // warp id within the half

    const size_t row  = (size_t)blockIdx.x * 2 + sub;
    const size_t base = row * S_LEN + (size_t)st * PER;

    // ---- 3 independent 256-bit streaming loads, issued before any math ----
    float fv[PER], zv[PER], iv[PER];
    ldg256_cs(fv, f  + base);
    ldg256_cs(zv, z  + base);
    ldg256_cs(iv, i_ + base);

    float xv[PER];
    #pragma unroll
    for (int j = 0; j < PER; j++) xv[j] = iv[j] * zv[j];

    // ---- Local chunk -> affine pair (A, B): h_out = A*h_in + B ----
    float A = 1.0f, Bc = 0.0f;
    #pragma unroll
    for (int j = 0; j < PER; j++) {
        Bc = fmaf(fv[j], Bc, xv[j]);
        A  = A * fv[j];
    }

    // ---- Intra-warp inclusive scan over pairs ----
    // combine(prev=(Ap,Bp), cur=(Ac,Bc)) = (Ap*Ac, Ac*Bp + Bc)
    float Ai = A, Bi = Bc;
    #pragma unroll
    for (int d = 1; d < 32; d <<= 1) {
        float Au = __shfl_up_sync(0xffffffffu, Ai, d);
        float Bu = __shfl_up_sync(0xffffffffu, Bi, d);
        if (lane >= d) {
            Bi = fmaf(Ai, Bu, Bi);
            Ai = Ai * Au;
        }
    }

    // ---- Cross-warp prefix: per-half smem + per-half NAMED barrier ----
    __shared__ float sA[2][NWARP];
    __shared__ float sB[2][NWARP];
    if (lane == 31) { sA[sub][warp] = Ai; sB[sub][warp] = Bi; }
    // Named barrier: only this half's 256 threads participate.
    asm volatile("bar.sync %0, %1;" :: "r"(sub + 1), "r"(HALF) : "memory");

    // Exclusive prefix over warps; only the B component matters (h0 = 0).
    float Bw = 0.0f;
    #pragma unroll
    for (int w = 0; w < NWARP; w++) {
        if (w < warp) {
            Bw = fmaf(sA[sub][w], Bw, sB[sub][w]);
        }
    }

    // ---- Thread's exclusive prefix within warp ----
    float Ae = __shfl_up_sync(0xffffffffu, Ai, 1);
    float Be = __shfl_up_sync(0xffffffffu, Bi, 1);
    if (lane == 0) { Ae = 1.0f; Be = 0.0f; }

    // Incoming h for this chunk (h0 = 0): h_in = Ae*Bw + Be
    float h = fmaf(Ae, Bw, Be);

    // ---- Replay chunk from registers, one 256-bit streaming store ----
    float ov[PER];
    #pragma unroll
    for (int j = 0; j < PER; j++) {
        h = fmaf(fv[j], h, xv[j]);
        ov[j] = h;
    }

    stg256_cs(out + base, ov);
}

extern "C" void kernel_launch(void* const* d_in, const int* in_sizes, int n_in,
                              void* d_out, int out_size)
{
    const float* f = (const float*)d_in[0];
    const float* z = (const float*)d_in[1];
    const float* i = (const float*)d_in[2];
    float* out = (float*)d_out;

    const int n_rows = in_sizes[0] / S_LEN;   // B*H = 16384 (even)
    ifo_scan_kernel<<<n_rows / 2, NTHR>>>(f, z, i, out);
}